// round 7
// baseline (speedup 1.0000x reference)
#include <cuda_runtime.h>
#include <cstdint>

#define THREADS 256
#define TB 4
#define NJ 12
#define DM 128
#define NH 4
#define HD 32
#define MR 48              // rows per CTA = TB*NJ

#define TSTR 132           // tile stride (floats)
#define QSTR 100           // scalar QKV stride

// float offsets
#define OFF_X    0                        // 48 x 132 = 6336
#define OFF_W    (OFF_X + MR*TSTR)        // 6336 : Wqkv 96 x 132 = 12672
#define OFF_QKV  OFF_W                    // overlay: 48 x 100 = 4800
#define OFF_AO   (OFF_W + 96*TSTR)        // 19008 : AO 48 x 132 = 6336
#define OFF_BQ   (OFF_AO + MR*TSTR)       // 25344
#define OFF_BK   (OFF_BQ + DM)
#define OFF_BV   (OFF_BK + DM)
#define OFF_BO   (OFF_BV + DM)
#define OFF_ADJ  (OFF_BO + DM)            // 144
#define OFF_KM   (OFF_ADJ + NJ*NJ)        // 48
#define SM_FLOATS (OFF_KM + MR)           // 26048 floats = 104192 B
#define OFF_WO   OFF_X                    // final Wo 128x132=16896 <= 19008 (X|W)

__device__ __forceinline__ float tf32r(float f) {
    unsigned r; asm("cvt.rna.tf32.f32 %0, %1;" : "=r"(r) : "f"(f));
    return __uint_as_float(r);
}
__device__ __forceinline__ float4 tf32r4(float4 v) {
    return make_float4(tf32r(v.x), tf32r(v.y), tf32r(v.z), tf32r(v.w));
}
__device__ __forceinline__ void ldsm_x4(uint32_t* r, uint32_t addr) {
    asm volatile("ldmatrix.sync.aligned.m8n8.x4.shared.b16 {%0,%1,%2,%3}, [%4];"
        : "=r"(r[0]), "=r"(r[1]), "=r"(r[2]), "=r"(r[3]) : "r"(addr));
}
__device__ __forceinline__ void mma8(float* d, const uint32_t* a, const uint32_t* b) {
    asm volatile(
        "mma.sync.aligned.m16n8k8.row.col.f32.tf32.tf32.f32 "
        "{%0,%1,%2,%3}, {%4,%5,%6,%7}, {%8,%9}, {%0,%1,%2,%3};"
        : "+f"(d[0]), "+f"(d[1]), "+f"(d[2]), "+f"(d[3])
        : "r"(a[0]), "r"(a[1]), "r"(a[2]), "r"(a[3]), "r"(b[0]), "r"(b[1]));
}

__global__ void __launch_bounds__(THREADS, 2)
cross_joint_attn_kernel(
    const float* __restrict__ x, const float* __restrict__ vis,
    const float* __restrict__ Wq, const float* __restrict__ bq,
    const float* __restrict__ Wk, const float* __restrict__ bk,
    const float* __restrict__ Wv, const float* __restrict__ bv,
    const float* __restrict__ Wo, const float* __restrict__ bo,
    const float* __restrict__ bias_scale, const float* __restrict__ adj,
    float* __restrict__ out)
{
    extern __shared__ __align__(16) float sm[];
    float* Xs   = sm + OFF_X;
    float* Ws   = sm + OFF_W;
    float* QKV  = sm + OFF_QKV;
    float* AOs  = sm + OFF_AO;
    float* WOs  = sm + OFF_WO;
    float* bqs  = sm + OFF_BQ;
    float* bks  = sm + OFF_BK;
    float* bvs  = sm + OFF_BV;
    float* bos  = sm + OFF_BO;
    float* adjb = sm + OFF_ADJ;
    float* kmsk = sm + OFF_KM;

    const int tid  = threadIdx.x;
    const int lane = tid & 31;
    const int warp = tid >> 5;
    const int cta  = blockIdx.x;
    const int gid  = lane >> 2;
    const int tig  = lane & 3;

    const uint32_t sb   = (uint32_t)__cvta_generic_to_shared(sm);
    const uint32_t sbX  = sb + OFF_X * 4;
    const uint32_t sbW  = sb + OFF_W * 4;
    const uint32_t sbAO = sb + OFF_AO * 4;
    const uint32_t sbWO = sb + OFF_WO * 4;

    // ---- stage X (48x128 tf32) ----
    {
        const float4* xg = (const float4*)(x + (size_t)cta * MR * DM);
        #pragma unroll
        for (int j = 0; j < 6; j++) {
            int i = tid + j * THREADS;            // < 1536
            int row = i >> 5, kk = (i & 31) * 4;
            *(float4*)(Xs + row * TSTR + kk) = tf32r4(xg[i]);
        }
    }
    // ---- stage W head 0 (96x128) ----
    #pragma unroll
    for (int j = 0; j < 12; j++) {
        int i = tid + j * THREADS;                // < 3072
        int row = i >> 5, kk = (i & 31) * 4;
        const float* src = (row < 32) ? (Wq + (size_t)row * DM)
                         : (row < 64) ? (Wk + (size_t)(row - 32) * DM)
                                      : (Wv + (size_t)(row - 64) * DM);
        *(float4*)(Ws + row * TSTR + kk) = tf32r4(*(const float4*)(src + kk));
    }
    if (tid < DM) {
        bqs[tid] = bq[tid]; bks[tid] = bk[tid];
        bvs[tid] = bv[tid]; bos[tid] = bo[tid];
    }
    if (tid < NJ * NJ) adjb[tid] = adj[tid] * bias_scale[0];
    if (tid < MR)      kmsk[tid] = -10.0f * (1.0f - vis[(size_t)cta * MR + tid]);
    __syncthreads();

    for (int h = 0; h < NH; ++h) {
        // ===== GEMM1 (warps 0..5, mg3 x ng2): QKV(48x96) = X @ Wqkv^T =====
        float acc[6][4];
        int mg = 0, ng = 0;
        if (warp < 6) {
            mg = warp >> 1; ng = warp & 1;
            uint32_t aaddr = sbX + (uint32_t)((mg * 16 + (lane & 15)) * TSTR) * 4
                                 + ((lane >> 4) * 16);
            uint32_t baddr[3];
            #pragma unroll
            for (int j = 0; j < 3; j++) {
                int quad = lane >> 3;
                int row = ng * 48 + j * 16 + (quad >> 1) * 8 + (lane & 7);
                baddr[j] = sbW + (uint32_t)(row * TSTR) * 4 + (quad & 1) * 16;
            }
            #pragma unroll
            for (int j = 0; j < 6; j++)
                #pragma unroll
                for (int r = 0; r < 4; r++) acc[j][r] = 0.0f;

            #pragma unroll
            for (int ks = 0; ks < 16; ks++) {
                uint32_t a[4], b[3][4];
                ldsm_x4(a, aaddr + ks * 32);
                #pragma unroll
                for (int j = 0; j < 3; j++) ldsm_x4(b[j], baddr[j] + ks * 32);
                #pragma unroll
                for (int j = 0; j < 3; j++) {
                    mma8(acc[2*j],   a, b[j]);
                    mma8(acc[2*j+1], a, b[j] + 2);
                }
            }
        }
        __syncthreads();   // all W reads done before QKV overlay writes

        if (warp < 6) {
            int row = mg * 16 + gid;
            #pragma unroll
            for (int j = 0; j < 6; j++) {
                int col = ng * 48 + j * 8 + 2 * tig;
                float b0, b1;
                if (col < 32)      { b0 = bqs[h*HD+col];    b1 = bqs[h*HD+col+1]; }
                else if (col < 64) { b0 = bks[h*HD+col-32]; b1 = bks[h*HD+col-31]; }
                else               { b0 = bvs[h*HD+col-64]; b1 = bvs[h*HD+col-63]; }
                *(float2*)(QKV + row * QSTR + col) =
                    make_float2(acc[j][0] + b0, acc[j][1] + b1);
                *(float2*)(QKV + (row + 8) * QSTR + col) =
                    make_float2(acc[j][2] + b0, acc[j][3] + b1);
            }
        }
        __syncthreads();

        // ===== attention: 4 threads per row (tid<192) =====
        if (tid < 192) {
            int row = tid >> 2, q = tid & 3;
            int lb = row / NJ, ln = row - lb * NJ;

            float qv[8];
            const float4* qp = (const float4*)(QKV + row * QSTR + q * 8);
            { float4 v0 = qp[0], v1 = qp[1];
              qv[0]=v0.x; qv[1]=v0.y; qv[2]=v0.z; qv[3]=v0.w;
              qv[4]=v1.x; qv[5]=v1.y; qv[6]=v1.z; qv[7]=v1.w; }

            float s[NJ];
            #pragma unroll
            for (int m = 0; m < NJ; m++) {
                const float4* kp = (const float4*)(QKV + (lb * NJ + m) * QSTR + 32 + q * 8);
                float4 v0 = kp[0], v1 = kp[1];
                float dot = qv[0]*v0.x + qv[1]*v0.y + qv[2]*v0.z + qv[3]*v0.w
                          + qv[4]*v1.x + qv[5]*v1.y + qv[6]*v1.z + qv[7]*v1.w;
                dot += __shfl_xor_sync(0xFFFFFFFFu, dot, 1);
                dot += __shfl_xor_sync(0xFFFFFFFFu, dot, 2);
                s[m] = dot * 0.17677669529663687f + adjb[ln * NJ + m] + kmsk[lb * NJ + m];
            }
            float mx = s[0];
            #pragma unroll
            for (int m = 1; m < NJ; m++) mx = fmaxf(mx, s[m]);
            float sum = 0.0f;
            #pragma unroll
            for (int m = 0; m < NJ; m++) { s[m] = __expf(s[m] - mx); sum += s[m]; }
            float inv = 1.0f / sum;

            float ao[8];
            #pragma unroll
            for (int j = 0; j < 8; j++) ao[j] = 0.0f;
            #pragma unroll
            for (int m = 0; m < NJ; m++) {
                float p = s[m] * inv;
                const float4* vp = (const float4*)(QKV + (lb * NJ + m) * QSTR + 64 + q * 8);
                float4 v0 = vp[0], v1 = vp[1];
                ao[0] += p*v0.x; ao[1] += p*v0.y; ao[2] += p*v0.z; ao[3] += p*v0.w;
                ao[4] += p*v1.x; ao[5] += p*v1.y; ao[6] += p*v1.z; ao[7] += p*v1.w;
            }
            float* dst = AOs + row * TSTR + h * HD + q * 8;
            *(float4*)(dst)     = make_float4(tf32r(ao[0]), tf32r(ao[1]), tf32r(ao[2]), tf32r(ao[3]));
            *(float4*)(dst + 4) = make_float4(tf32r(ao[4]), tf32r(ao[5]), tf32r(ao[6]), tf32r(ao[7]));
        }
        __syncthreads();   // QKV reads done before W_{h+1} staging overwrites

        if (h < 3) {
            #pragma unroll
            for (int j = 0; j < 12; j++) {
                int i = tid + j * THREADS;
                int row = i >> 5, kk = (i & 31) * 4;
                const float* src = (row < 32) ? (Wq + (size_t)((h+1) * HD + row) * DM)
                                 : (row < 64) ? (Wk + (size_t)((h+1) * HD + row - 32) * DM)
                                              : (Wv + (size_t)((h+1) * HD + row - 64) * DM);
                *(float4*)(Ws + row * TSTR + kk) = tf32r4(*(const float4*)(src + kk));
            }
            __syncthreads();
        }
    }

    // ---- stage Wo (128x128) into freed X|W region ----
    #pragma unroll
    for (int j = 0; j < 16; j++) {
        int i = tid + j * THREADS;                 // < 4096
        int row = i >> 5, kk = (i & 31) * 4;
        *(float4*)(WOs + row * TSTR + kk) = tf32r4(*(const float4*)(Wo + (size_t)row * DM + kk));
    }
    __syncthreads();

    // ===== final GEMM (8 warps, N=16 each): Y(48x128) = AO @ Wo^T =====
    {
        uint32_t aaddr[3], baddr;
        #pragma unroll
        for (int i = 0; i < 3; i++)
            aaddr[i] = sbAO + (uint32_t)((i * 16 + (lane & 15)) * TSTR) * 4
                            + ((lane >> 4) * 16);
        {
            int quad = lane >> 3;
            int row = warp * 16 + (quad >> 1) * 8 + (lane & 7);
            baddr = sbWO + (uint32_t)(row * TSTR) * 4 + (quad & 1) * 16;
        }

        float y[3][2][4];
        #pragma unroll
        for (int i = 0; i < 3; i++)
            #pragma unroll
            for (int j = 0; j < 2; j++)
                #pragma unroll
                for (int r = 0; r < 4; r++) y[i][j][r] = 0.0f;

        #pragma unroll
        for (int ks = 0; ks < 16; ks++) {
            uint32_t a[3][4], b[4];
            #pragma unroll
            for (int i = 0; i < 3; i++) ldsm_x4(a[i], aaddr[i] + ks * 32);
            ldsm_x4(b, baddr + ks * 32);
            #pragma unroll
            for (int i = 0; i < 3; i++) {
                mma8(y[i][0], a[i], b);
                mma8(y[i][1], a[i], b + 2);
            }
        }

        #pragma unroll
        for (int i = 0; i < 3; i++) {
            int row = i * 16 + gid;
            #pragma unroll
            for (int j = 0; j < 2; j++) {
                int col = warp * 16 + j * 8 + 2 * tig;
                float b0 = bos[col], b1 = bos[col + 1];
                size_t base = ((size_t)cta * MR + row) * DM + col;
                *(float2*)(out + base)          = make_float2(y[i][j][0] + b0, y[i][j][1] + b1);
                *(float2*)(out + base + 8 * DM) = make_float2(y[i][j][2] + b0, y[i][j][3] + b1);
            }
        }
    }
}

extern "C" void kernel_launch(void* const* d_in, const int* in_sizes, int n_in,
                              void* d_out, int out_size) {
    const float* x   = (const float*)d_in[0];
    const float* vis = (const float*)d_in[1];
    const float* Wq  = (const float*)d_in[2];
    const float* bq  = (const float*)d_in[3];
    const float* Wk  = (const float*)d_in[4];
    const float* bk  = (const float*)d_in[5];
    const float* Wv  = (const float*)d_in[6];
    const float* bv  = (const float*)d_in[7];
    const float* Wo  = (const float*)d_in[8];
    const float* bo  = (const float*)d_in[9];
    const float* bsc = (const float*)d_in[10];
    const float* adj = (const float*)d_in[11];
    float* out = (float*)d_out;

    const int B = in_sizes[0] / (NJ * DM);        // 16384
    const int grid = B / TB;                      // 4096
    const size_t smem = SM_FLOATS * sizeof(float);    // 104192 B

    static bool attr_set = false;
    if (!attr_set) {
        cudaFuncSetAttribute(cross_joint_attn_kernel,
                             cudaFuncAttributeMaxDynamicSharedMemorySize, (int)smem);
        attr_set = true;
    }
    cross_joint_attn_kernel<<<grid, THREADS, smem>>>(
        x, vis, Wq, bq, Wk, bk, Wv, bv, Wo, bo, bsc, adj, out);
}

// round 8
// speedup vs baseline: 1.8250x; 1.8250x over previous
#include <cuda_runtime.h>
#include <cuda_fp16.h>
#include <cstdint>

#define THREADS 256
#define TB 8
#define NJ 12
#define DM 128
#define NH 4
#define HD 32
#define MR 96              // rows per CTA = TB*NJ

#define TSTR 136           // fp16 tile stride (halves): 272B, 272%128=16 -> ldsm conflict-free
#define QSTR 104           // fp16 QKV stride (halves): 208B, 16B-aligned rows

// byte offsets
#define OFF_X    0                         // 96 x 136 halves = 26112 B
#define OFF_W    26112                     // 96 x 136 halves
#define OFF_QKV  52224                     // 96 x 104 halves = 19968 B
#define OFF_AO   72192                     // 96 x 136 halves = 26112 B
#define OFF_WO   0                         // final Wo 128x136 halves = 34816 B (overlays X|W)
#define OFF_BQ   98304                     // fp32 arrays below
#define OFF_BK   98816
#define OFF_BV   99328
#define OFF_BO   99840
#define OFF_ADJ  100352                    // 144 fp32
#define OFF_KM   100928                    // 96 fp32
#define SMEM_BYTES 101376

__device__ __forceinline__ uint2 f4_to_h4(float4 v) {
    __half2 a = __floats2half2_rn(v.x, v.y);
    __half2 b = __floats2half2_rn(v.z, v.w);
    uint2 r;
    r.x = *(uint32_t*)&a; r.y = *(uint32_t*)&b;
    return r;
}

__device__ __forceinline__ void ldsm_x4(uint32_t* r, uint32_t addr) {
    asm volatile("ldmatrix.sync.aligned.m8n8.x4.shared.b16 {%0,%1,%2,%3}, [%4];"
        : "=r"(r[0]), "=r"(r[1]), "=r"(r[2]), "=r"(r[3]) : "r"(addr));
}
__device__ __forceinline__ void mma16(float* d, const uint32_t* a, const uint32_t* b) {
    asm volatile(
        "mma.sync.aligned.m16n8k16.row.col.f32.f16.f16.f32 "
        "{%0,%1,%2,%3}, {%4,%5,%6,%7}, {%8,%9}, {%0,%1,%2,%3};"
        : "+f"(d[0]), "+f"(d[1]), "+f"(d[2]), "+f"(d[3])
        : "r"(a[0]), "r"(a[1]), "r"(a[2]), "r"(a[3]), "r"(b[0]), "r"(b[1]));
}

__global__ void __launch_bounds__(THREADS, 2)
cross_joint_attn_kernel(
    const float* __restrict__ x, const float* __restrict__ vis,
    const float* __restrict__ Wq, const float* __restrict__ bq,
    const float* __restrict__ Wk, const float* __restrict__ bk,
    const float* __restrict__ Wv, const float* __restrict__ bv,
    const float* __restrict__ Wo, const float* __restrict__ bo,
    const float* __restrict__ bias_scale, const float* __restrict__ adj,
    float* __restrict__ out)
{
    extern __shared__ __align__(16) char smc[];
    __half* Xh  = (__half*)(smc + OFF_X);
    __half* Wh  = (__half*)(smc + OFF_W);
    __half* QKV = (__half*)(smc + OFF_QKV);
    __half* AOh = (__half*)(smc + OFF_AO);
    __half* WOh = (__half*)(smc + OFF_WO);
    float* bqs  = (float*)(smc + OFF_BQ);
    float* bks  = (float*)(smc + OFF_BK);
    float* bvs  = (float*)(smc + OFF_BV);
    float* bos  = (float*)(smc + OFF_BO);
    float* adjb = (float*)(smc + OFF_ADJ);
    float* kmsk = (float*)(smc + OFF_KM);

    const int tid  = threadIdx.x;
    const int lane = tid & 31;
    const int warp = tid >> 5;
    const int cta  = blockIdx.x;
    const int gid  = lane >> 2;
    const int tig  = lane & 3;

    const uint32_t sb   = (uint32_t)__cvta_generic_to_shared(smc);
    const uint32_t sbX  = sb + OFF_X;
    const uint32_t sbW  = sb + OFF_W;
    const uint32_t sbAO = sb + OFF_AO;
    const uint32_t sbWO = sb + OFF_WO;

    // ---- stage X (96x128 fp16) ----
    {
        const float4* xg = (const float4*)(x + (size_t)cta * MR * DM);
        #pragma unroll
        for (int j = 0; j < 12; j++) {
            int i = tid + j * THREADS;              // < 3072
            int row = i >> 5, kk = (i & 31) * 4;
            *(uint2*)(Xh + row * TSTR + kk) = f4_to_h4(xg[i]);
        }
    }
    // ---- stage W head 0 (96x128 fp16) ----
    #pragma unroll
    for (int j = 0; j < 12; j++) {
        int i = tid + j * THREADS;
        int row = i >> 5, kk = (i & 31) * 4;
        const float* src = (row < 32) ? (Wq + (size_t)row * DM)
                         : (row < 64) ? (Wk + (size_t)(row - 32) * DM)
                                      : (Wv + (size_t)(row - 64) * DM);
        *(uint2*)(Wh + row * TSTR + kk) = f4_to_h4(*(const float4*)(src + kk));
    }
    if (tid < DM) {
        bqs[tid] = bq[tid]; bks[tid] = bk[tid];
        bvs[tid] = bv[tid]; bos[tid] = bo[tid];
    }
    if (tid < NJ * NJ) adjb[tid] = adj[tid] * bias_scale[0];
    if (tid < MR)      kmsk[tid] = -10.0f * (1.0f - vis[(size_t)cta * MR + tid]);
    __syncthreads();

    for (int h = 0; h < NH; ++h) {
        // ===== GEMM1 (warps 0..5, mg2 x ng3): QKV(96x96) = X @ Wqkv^T =====
        if (warp < 6) {
            const int mg = warp / 3, ng = warp - mg * 3;
            uint32_t aaddr[3], baddr[2];
            #pragma unroll
            for (int i = 0; i < 3; i++)
                aaddr[i] = sbX + (uint32_t)((mg * 48 + i * 16 + (lane & 15)) * TSTR) * 2
                               + ((lane >> 4) * 16);
            #pragma unroll
            for (int j = 0; j < 2; j++) {
                int row = ng * 32 + j * 16 + (lane & 7) + ((lane >> 4) * 8);
                baddr[j] = sbW + (uint32_t)(row * TSTR) * 2 + (((lane >> 3) & 1) * 16);
            }

            float acc[3][4][4];
            #pragma unroll
            for (int i = 0; i < 3; i++)
                #pragma unroll
                for (int j = 0; j < 4; j++)
                    #pragma unroll
                    for (int r = 0; r < 4; r++) acc[i][j][r] = 0.0f;

            #pragma unroll
            for (int ks = 0; ks < 8; ks++) {
                uint32_t a[3][4], b[2][4];
                #pragma unroll
                for (int i = 0; i < 3; i++) ldsm_x4(a[i], aaddr[i] + ks * 32);
                #pragma unroll
                for (int j = 0; j < 2; j++) ldsm_x4(b[j], baddr[j] + ks * 32);
                #pragma unroll
                for (int i = 0; i < 3; i++)
                    #pragma unroll
                    for (int j = 0; j < 2; j++) {
                        mma16(acc[i][2*j],   a[i], b[j]);
                        mma16(acc[i][2*j+1], a[i], b[j] + 2);
                    }
            }
            // bias + scatter to fp16 QKV
            #pragma unroll
            for (int i = 0; i < 3; i++) {
                int row = mg * 48 + i * 16 + gid;
                #pragma unroll
                for (int j = 0; j < 4; j++) {
                    int col = ng * 32 + j * 8 + 2 * tig;
                    float b0, b1;
                    if (col < 32)      { b0 = bqs[h*HD+col];    b1 = bqs[h*HD+col+1]; }
                    else if (col < 64) { b0 = bks[h*HD+col-32]; b1 = bks[h*HD+col-31]; }
                    else               { b0 = bvs[h*HD+col-64]; b1 = bvs[h*HD+col-63]; }
                    __half2 lo = __floats2half2_rn(acc[i][j][0] + b0, acc[i][j][1] + b1);
                    __half2 hi = __floats2half2_rn(acc[i][j][2] + b0, acc[i][j][3] + b1);
                    *(__half2*)(QKV + row * QSTR + col)       = lo;
                    *(__half2*)(QKV + (row + 8) * QSTR + col) = hi;
                }
            }
        }
        __syncthreads();

        // ===== attention (tid<192, 2 threads/row) || stage W_{h+1} (warps 6,7) =====
        if (tid < 192) {
            int row  = tid >> 1;
            int half = tid & 1;
            int lb = row / NJ, ln = row - lb * NJ;

            float q[16];
            {
                const uint4* qp = (const uint4*)(QKV + row * QSTR + half * 16);
                uint4 u0 = qp[0], u1 = qp[1];
                const __half2* hp0 = (const __half2*)&u0;
                const __half2* hp1 = (const __half2*)&u1;
                #pragma unroll
                for (int j = 0; j < 4; j++) {
                    float2 f0 = __half22float2(hp0[j]);
                    float2 f1 = __half22float2(hp1[j]);
                    q[2*j] = f0.x; q[2*j+1] = f0.y;
                    q[8+2*j] = f1.x; q[8+2*j+1] = f1.y;
                }
            }
            float s[NJ];
            #pragma unroll
            for (int m = 0; m < NJ; m++) {
                const uint4* kp = (const uint4*)(QKV + (lb * NJ + m) * QSTR + 32 + half * 16);
                uint4 u0 = kp[0], u1 = kp[1];
                const __half2* hp0 = (const __half2*)&u0;
                const __half2* hp1 = (const __half2*)&u1;
                float dot = 0.0f;
                #pragma unroll
                for (int j = 0; j < 4; j++) {
                    float2 f0 = __half22float2(hp0[j]);
                    float2 f1 = __half22float2(hp1[j]);
                    dot += q[2*j]*f0.x + q[2*j+1]*f0.y + q[8+2*j]*f1.x + q[8+2*j+1]*f1.y;
                }
                dot += __shfl_xor_sync(0xFFFFFFFFu, dot, 1);
                s[m] = dot * 0.17677669529663687f + adjb[ln * NJ + m] + kmsk[lb * NJ + m];
            }
            float mx = s[0];
            #pragma unroll
            for (int m = 1; m < NJ; m++) mx = fmaxf(mx, s[m]);
            float sum = 0.0f;
            #pragma unroll
            for (int m = 0; m < NJ; m++) { s[m] = __expf(s[m] - mx); sum += s[m]; }
            float inv = 1.0f / sum;

            float ao[16];
            #pragma unroll
            for (int j = 0; j < 16; j++) ao[j] = 0.0f;
            #pragma unroll
            for (int m = 0; m < NJ; m++) {
                float p = s[m] * inv;
                const uint4* vp = (const uint4*)(QKV + (lb * NJ + m) * QSTR + 64 + half * 16);
                uint4 u0 = vp[0], u1 = vp[1];
                const __half2* hp0 = (const __half2*)&u0;
                const __half2* hp1 = (const __half2*)&u1;
                #pragma unroll
                for (int j = 0; j < 4; j++) {
                    float2 f0 = __half22float2(hp0[j]);
                    float2 f1 = __half22float2(hp1[j]);
                    ao[2*j]   += p * f0.x; ao[2*j+1]   += p * f0.y;
                    ao[8+2*j] += p * f1.x; ao[8+2*j+1] += p * f1.y;
                }
            }
            __half* dst = AOh + row * TSTR + h * HD + half * 16;
            #pragma unroll
            for (int j = 0; j < 4; j++)
                *(__half2*)(dst + 2*j) = __floats2half2_rn(ao[2*j], ao[2*j+1]);
            #pragma unroll
            for (int j = 0; j < 4; j++)
                *(__half2*)(dst + 8 + 2*j) = __floats2half2_rn(ao[8+2*j], ao[8+2*j+1]);
        } else if (h < 3) {
            // warps 6,7: stage next head's Wqkv
            int t2 = tid - 192;
            #pragma unroll
            for (int j = 0; j < 48; j++) {
                int i = t2 + j * 64;                 // < 3072
                int row = i >> 5, kk = (i & 31) * 4;
                const float* src = (row < 32) ? (Wq + (size_t)((h+1) * HD + row) * DM)
                                 : (row < 64) ? (Wk + (size_t)((h+1) * HD + row - 32) * DM)
                                              : (Wv + (size_t)((h+1) * HD + row - 64) * DM);
                *(uint2*)(Wh + row * TSTR + kk) = f4_to_h4(*(const float4*)(src + kk));
            }
        }
        __syncthreads();
    }

    // ---- stage Wo (128x128 fp16) into freed X|W region ----
    #pragma unroll
    for (int j = 0; j < 16; j++) {
        int i = tid + j * THREADS;                  // < 4096
        int row = i >> 5, kk = (i & 31) * 4;
        *(uint2*)(WOh + row * TSTR + kk) = f4_to_h4(*(const float4*)(Wo + (size_t)row * DM + kk));
    }
    __syncthreads();

    // ===== final GEMM (8 warps, mg2 x ng4): Y(96x128) = AO @ Wo^T =====
    {
        const int fmg = warp >> 2, fng = warp & 3;
        uint32_t aaddr[3], baddr[2];
        #pragma unroll
        for (int i = 0; i < 3; i++)
            aaddr[i] = sbAO + (uint32_t)((fmg * 48 + i * 16 + (lane & 15)) * TSTR) * 2
                            + ((lane >> 4) * 16);
        #pragma unroll
        for (int j = 0; j < 2; j++) {
            int row = fng * 32 + j * 16 + (lane & 7) + ((lane >> 4) * 8);
            baddr[j] = sbWO + (uint32_t)(row * TSTR) * 2 + (((lane >> 3) & 1) * 16);
        }

        float y[3][4][4];
        #pragma unroll
        for (int i = 0; i < 3; i++)
            #pragma unroll
            for (int j = 0; j < 4; j++)
                #pragma unroll
                for (int r = 0; r < 4; r++) y[i][j][r] = 0.0f;

        #pragma unroll
        for (int ks = 0; ks < 8; ks++) {
            uint32_t a[3][4], b[2][4];
            #pragma unroll
            for (int i = 0; i < 3; i++) ldsm_x4(a[i], aaddr[i] + ks * 32);
            #pragma unroll
            for (int j = 0; j < 2; j++) ldsm_x4(b[j], baddr[j] + ks * 32);
            #pragma unroll
            for (int i = 0; i < 3; i++)
                #pragma unroll
                for (int j = 0; j < 2; j++) {
                    mma16(y[i][2*j],   a[i], b[j]);
                    mma16(y[i][2*j+1], a[i], b[j] + 2);
                }
        }

        // epilogue: y + bo -> global (fp32)
        #pragma unroll
        for (int i = 0; i < 3; i++) {
            int row = fmg * 48 + i * 16 + gid;
            #pragma unroll
            for (int j = 0; j < 4; j++) {
                int col = fng * 32 + j * 8 + 2 * tig;
                float b0 = bos[col], b1 = bos[col + 1];
                size_t base = ((size_t)cta * MR + row) * DM + col;
                *(float2*)(out + base)          = make_float2(y[i][j][0] + b0, y[i][j][1] + b1);
                *(float2*)(out + base + 8 * DM) = make_float2(y[i][j][2] + b0, y[i][j][3] + b1);
            }
        }
    }
}

extern "C" void kernel_launch(void* const* d_in, const int* in_sizes, int n_in,
                              void* d_out, int out_size) {
    const float* x   = (const float*)d_in[0];
    const float* vis = (const float*)d_in[1];
    const float* Wq  = (const float*)d_in[2];
    const float* bq  = (const float*)d_in[3];
    const float* Wk  = (const float*)d_in[4];
    const float* bk  = (const float*)d_in[5];
    const float* Wv  = (const float*)d_in[6];
    const float* bv  = (const float*)d_in[7];
    const float* Wo  = (const float*)d_in[8];
    const float* bo  = (const float*)d_in[9];
    const float* bsc = (const float*)d_in[10];
    const float* adj = (const float*)d_in[11];
    float* out = (float*)d_out;

    const int B = in_sizes[0] / (NJ * DM);       // 16384
    const int grid = B / TB;                     // 2048

    static bool attr_set = false;
    if (!attr_set) {
        cudaFuncSetAttribute(cross_joint_attn_kernel,
                             cudaFuncAttributeMaxDynamicSharedMemorySize, SMEM_BYTES);
        attr_set = true;
    }
    cross_joint_attn_kernel<<<grid, THREADS, SMEM_BYTES>>>(
        x, vis, Wq, bq, Wk, bk, Wv, bv, Wo, bo, bsc, adj, out);
}